// round 16
// baseline (speedup 1.0000x reference)
#include <cuda_runtime.h>
#include <cuda_fp16.h>
#include <cstdint>

// EdgeModel fused 3-layer MLP via arch-agnostic mma.sync, single-pass fp16
// (f32 accumulate; rel_err 5.2e-4 verified R14).
// R15: L1tex was binding (74.6%). Fragment traffic ~ nw*(Mw+Nw): switch from
// 8 warps of 32x32 (8*64) to 4 warps of 64x32 (4*96) per 64x128 CTA tile:
// B-LDG duplication halves, A-LDSM unchanged => ~25% less fragment traffic,
// MMA:LDSM ratio 2->4. 128 threads, ~108 regs, 17.4KB smem -> 4 CTAs/SM
// (16 warps, 4 independent CTAs for phase masking).

#define DH 128
#define APAD 68
#define A_U32 (64 * APAD)             // 4352 u32 = 17408 B (fp16 A plane)

// fragment-ordered weight image (single fp16 plane), verified R13/R14:
// [region 0..4][ks 0..7][n8 0..15][lane 0..31][j 0..1]
// value(j) = half2(W[k][n], W[k+1][n]), k = ks*16 + 2*(l&3) + j*8,
//            n = n8*8 + (l>>2); regions 0..2 = W0 k-chunks, 3 = W1, 4 = W2.
__device__ __align__(16) uint32_t g_wf[5][8][16][32][2];

// ---------------- helpers ----------------
__device__ __forceinline__ uint32_t smem_u32p(const void* p) {
    uint32_t a;
    asm("{ .reg .u64 t; cvta.to.shared.u64 t, %1; cvt.u32.u64 %0, t; }"
        : "=r"(a) : "l"(p));
    return a;
}

__device__ __forceinline__ uint32_t pack_h2(float a0, float a1) {
    __half2 h = __floats2half2_rn(a0, a1);
    return *(uint32_t*)&h;
}

__device__ __forceinline__ float silu_f(float x) {
    return x / (1.0f + __expf(-x));
}

#define LDSM4(r, addr)                                                         \
    asm volatile("ldmatrix.sync.aligned.m8n8.x4.shared.b16 {%0,%1,%2,%3}, [%4];" \
        : "=r"((r)[0]), "=r"((r)[1]), "=r"((r)[2]), "=r"((r)[3]) : "r"(addr))

#define MMA16816(c, a, b0, b1)                                                 \
    asm volatile("mma.sync.aligned.m16n8k16.row.col.f32.f16.f16.f32 "          \
        "{%0,%1,%2,%3}, {%4,%5,%6,%7}, {%8,%9}, {%0,%1,%2,%3};"                \
        : "+f"((c)[0]), "+f"((c)[1]), "+f"((c)[2]), "+f"((c)[3])               \
        : "r"((a)[0]), "r"((a)[1]), "r"((a)[2]), "r"((a)[3]),                  \
          "r"(b0), "r"(b1))

// ---------------- prep: pack weights into fragment-ordered fp16 image -------
__global__ void prep_weights(const float* __restrict__ W0,
                             const float* __restrict__ W1,
                             const float* __restrict__ W2) {
    int i = blockIdx.x * blockDim.x + threadIdx.x;
    if (i >= 5 * 8 * 16 * 32 * 2) return;          // 40960
    int j  = i & 1;
    int l  = (i >> 1) & 31;
    int n8 = (i >> 6) & 15;
    int ks = (i >> 10) & 7;
    int r  = i >> 13;
    const float* W = (r < 3) ? W0 : (r == 3) ? W1 : W2;
    int n  = n8 * 8 + (l >> 2);
    int k0 = ((r < 3) ? r * 128 : 0) + ks * 16 + 2 * (l & 3) + j * 8;
    float v0 = W[(size_t)k0 * DH + n];
    float v1 = W[(size_t)(k0 + 1) * DH + n];
    g_wf[r][ks][n8][l][j] = pack_h2(v0, v1);
}

// ---------------- device pieces ----------------
// stage one 64-row fp32 chunk -> fp16 SMEM plane; 128 thr = (row, 64-col half)
__device__ __forceinline__ void stageA(uint32_t* A, const float* xp,
                                       int srow, int sq, int grow_s, bool sv) {
    const float4* p = (const float4*)(xp + (size_t)grow_s * DH + sq * 64);
    #pragma unroll
    for (int q = 0; q < 16; q++) {
        float4 v = sv ? p[q] : make_float4(0.f, 0.f, 0.f, 0.f);
        int kp = sq * 32 + 2 * q;
        A[srow * APAD + kp]     = pack_h2(v.x, v.y);
        A[srow * APAD + kp + 1] = pack_h2(v.z, v.w);
    }
}

// single-pass MMA chunk; warp tile 64x32: 4 A-frag LDSM + 4 B-frag LDG per ks,
// B registers reused across all 4 mt (16 MMAs per ks -> MMA:LDSM ratio 4).
__device__ __forceinline__ void mma_chunk(float acc[4][4][4], uint32_t aL,
                                          const uint32_t* __restrict__ wf,
                                          int n8base, int l) {
    #pragma unroll 2
    for (int ks = 0; ks < 8; ks++) {
        // B first (global latency overlaps the A ldsm latency)
        uint2 bh[4];
        const uint32_t* base = wf + ks * 1024 + n8base * 64 + l * 2;
        #pragma unroll
        for (int nt = 0; nt < 4; nt++)
            bh[nt] = __ldg((const uint2*)(base + nt * 64));
        uint32_t ah[4][4];
        #pragma unroll
        for (int mt = 0; mt < 4; mt++)
            LDSM4(ah[mt], aL + mt * (16 * APAD * 4) + ks * 32);
        #pragma unroll
        for (int mt = 0; mt < 4; mt++)
            #pragma unroll
            for (int nt = 0; nt < 4; nt++)
                MMA16816(acc[mt][nt], ah[mt], bh[nt].x, bh[nt].y);
    }
}

// ---------------- fused MLP kernel ----------------
__global__ void __launch_bounds__(128, 4)
mlp_kernel(const float* __restrict__ src, const float* __restrict__ dst,
           const float* __restrict__ edg,
           const float* __restrict__ b0, const float* __restrict__ b1,
           const float* __restrict__ b2,
           float* __restrict__ out, int E)
{
    __shared__ __align__(16) uint32_t sA[A_U32];   // 17408 B

    const int tid = threadIdx.x;
    const int l = tid & 31, w = tid >> 5;          // 4 warps
    const int warp_n = w * 32;
    const int n8base = w * 4;
    const int tile = blockIdx.x;

    // ldmatrix A per-lane offsets (verified mapping; warp_m = 0, mt spans 64)
    const int laneA_r = (l & 7) + ((l >> 3) & 1) * 8;
    const int laneA_k = ((l >> 4) & 1) * 4;
    const uint32_t aL = smem_u32p(sA) + (laneA_r * APAD + laneA_k) * 4;

    float acc[4][4][4];
    #pragma unroll
    for (int mt = 0; mt < 4; mt++)
        #pragma unroll
        for (int nt = 0; nt < 4; nt++)
            #pragma unroll
            for (int q = 0; q < 4; q++) acc[mt][nt][q] = 0.f;

    // A staging map: 128 thr -> (row 0..63, 64-col half)
    const int srow = tid >> 1, sq = tid & 1;
    const int grow_s = tile * 64 + srow;
    const bool svalid = grow_s < E;

    // epilogue lane constants (verified formulas; warp_m = 0)
    const int er0 = (l >> 2);
    const int ec  = (l & 3) * 2;
    const int ecp = (warp_n >> 1) + (l & 3);

    // ================= layer 0: 3 k-chunks (edge, src, dest) ================
    #pragma unroll 1
    for (int c = 0; c < 3; c++) {
        const float* xp = (c == 0) ? edg : (c == 1) ? src : dst;
        stageA(sA, xp, srow, sq, grow_s, svalid);
        __syncthreads();
        mma_chunk(acc, aL, &g_wf[c][0][0][0][0], n8base, l);
        __syncthreads();
    }

    // =============== layers 1 & 2 ===============
    #pragma unroll 1
    for (int layer = 1; layer <= 2; layer++) {
        const float* bias = (layer == 1) ? b0 : b1;   // bias of the PREVIOUS gemm
        // epilogue: silu(acc + bias) -> A ; reset acc
        #pragma unroll
        for (int mt = 0; mt < 4; mt++)
            #pragma unroll
            for (int nt = 0; nt < 4; nt++) {
                int col = warp_n + 8 * nt + ec;
                float bb0 = __ldg(bias + col), bb1 = __ldg(bias + col + 1);
                int r0 = 16 * mt + er0;
                int cp = ecp + 4 * nt;
                float h00 = silu_f(acc[mt][nt][0] + bb0);
                float h01 = silu_f(acc[mt][nt][1] + bb1);
                float h10 = silu_f(acc[mt][nt][2] + bb0);
                float h11 = silu_f(acc[mt][nt][3] + bb1);
                sA[r0 * APAD + cp]       = pack_h2(h00, h01);
                sA[(r0 + 8) * APAD + cp] = pack_h2(h10, h11);
                acc[mt][nt][0] = 0.f; acc[mt][nt][1] = 0.f;
                acc[mt][nt][2] = 0.f; acc[mt][nt][3] = 0.f;
            }
        __syncthreads();
        mma_chunk(acc, aL, &g_wf[layer + 2][0][0][0][0], n8base, l);
        __syncthreads();
    }

    // =============== final epilogue: acc + b2 -> out ===============
    #pragma unroll
    for (int mt = 0; mt < 4; mt++)
        #pragma unroll
        for (int nt = 0; nt < 4; nt++) {
            int col = warp_n + 8 * nt + ec;
            float bb0 = __ldg(b2 + col), bb1 = __ldg(b2 + col + 1);
            int r0g = tile * 64 + 16 * mt + er0;
            if (r0g < E) {
                float2 v = { acc[mt][nt][0] + bb0, acc[mt][nt][1] + bb1 };
                *(float2*)(out + (size_t)r0g * DH + col) = v;
            }
            if (r0g + 8 < E) {
                float2 v = { acc[mt][nt][2] + bb0, acc[mt][nt][3] + bb1 };
                *(float2*)(out + (size_t)(r0g + 8) * DH + col) = v;
            }
        }
}

// ---------------- host ----------------
extern "C" void kernel_launch(void* const* d_in, const int* in_sizes, int n_in,
                              void* d_out, int out_size) {
    const float* src = (const float*)d_in[0];
    const float* dst = (const float*)d_in[1];
    const float* edg = (const float*)d_in[2];
    const float* W0  = (const float*)d_in[3];
    const float* b0  = (const float*)d_in[4];
    const float* W1  = (const float*)d_in[5];
    const float* b1  = (const float*)d_in[6];
    const float* W2  = (const float*)d_in[7];
    const float* b2  = (const float*)d_in[8];

    int E = in_sizes[0] / DH;
    int ntiles = (E + 63) / 64;

    prep_weights<<<(40960 + 255) / 256, 256>>>(W0, W1, W2);
    mlp_kernel<<<ntiles, 128>>>(src, dst, edg, b0, b1, b2, (float*)d_out, E);
}

// round 17
// speedup vs baseline: 1.6089x; 1.6089x over previous
#include <cuda_runtime.h>
#include <cuda_fp16.h>
#include <cstdint>

// EdgeModel fused 3-layer MLP via arch-agnostic mma.sync, single-pass fp16
// (f32 accumulate; rel_err 5.23e-4 verified R14).
// R16: exact R14 geometry (256 thr, 8 warps of 32x32, 64 regs, 4 CTAs/SM =
// 32 warps -- R15 proved warp count beats per-warp efficiency here), plus a
// second A buffer so every stage/epilogue writes the buffer peers are NOT
// reading: 10 syncthreads/tile -> 5, and layer-0 staging LDGs issue straight
// after each warp's MMA instead of behind a barrier. smem 34.8KB/CTA keeps
// 4 CTAs/SM. Reg-neutral by construction.

#define DH 128
#define APAD 68
#define A_U32 (64 * APAD)             // 4352 u32 = 17408 B (one fp16 A plane)

// fragment-ordered weight image (single fp16 plane), verified R13/R14:
// [region 0..4][ks 0..7][n8 0..15][lane 0..31][j 0..1]
// value(j) = half2(W[k][n], W[k+1][n]), k = ks*16 + 2*(l&3) + j*8,
//            n = n8*8 + (l>>2); regions 0..2 = W0 k-chunks, 3 = W1, 4 = W2.
__device__ __align__(16) uint32_t g_wf[5][8][16][32][2];

// ---------------- helpers ----------------
__device__ __forceinline__ uint32_t smem_u32p(const void* p) {
    uint32_t a;
    asm("{ .reg .u64 t; cvta.to.shared.u64 t, %1; cvt.u32.u64 %0, t; }"
        : "=r"(a) : "l"(p));
    return a;
}

__device__ __forceinline__ uint32_t pack_h2(float a0, float a1) {
    __half2 h = __floats2half2_rn(a0, a1);
    return *(uint32_t*)&h;
}

__device__ __forceinline__ float silu_f(float x) {
    return x / (1.0f + __expf(-x));
}

#define LDSM4(r, addr)                                                         \
    asm volatile("ldmatrix.sync.aligned.m8n8.x4.shared.b16 {%0,%1,%2,%3}, [%4];" \
        : "=r"((r)[0]), "=r"((r)[1]), "=r"((r)[2]), "=r"((r)[3]) : "r"(addr))

#define MMA16816(c, a, b0, b1)                                                 \
    asm volatile("mma.sync.aligned.m16n8k16.row.col.f32.f16.f16.f32 "          \
        "{%0,%1,%2,%3}, {%4,%5,%6,%7}, {%8,%9}, {%0,%1,%2,%3};"                \
        : "+f"((c)[0]), "+f"((c)[1]), "+f"((c)[2]), "+f"((c)[3])               \
        : "r"((a)[0]), "r"((a)[1]), "r"((a)[2]), "r"((a)[3]),                  \
          "r"(b0), "r"(b1))

// ---------------- prep: pack weights into fragment-ordered fp16 image -------
__global__ void prep_weights(const float* __restrict__ W0,
                             const float* __restrict__ W1,
                             const float* __restrict__ W2) {
    int i = blockIdx.x * blockDim.x + threadIdx.x;
    if (i >= 5 * 8 * 16 * 32 * 2) return;          // 40960
    int j  = i & 1;
    int l  = (i >> 1) & 31;
    int n8 = (i >> 6) & 15;
    int ks = (i >> 10) & 7;
    int r  = i >> 13;
    const float* W = (r < 3) ? W0 : (r == 3) ? W1 : W2;
    int n  = n8 * 8 + (l >> 2);
    int k0 = ((r < 3) ? r * 128 : 0) + ks * 16 + 2 * (l & 3) + j * 8;
    float v0 = W[(size_t)k0 * DH + n];
    float v1 = W[(size_t)(k0 + 1) * DH + n];
    g_wf[r][ks][n8][l][j] = pack_h2(v0, v1);
}

// ---------------- device pieces ----------------
// stage one 64-row fp32 chunk -> fp16 SMEM plane (R14-verified layout)
__device__ __forceinline__ void stageA(uint32_t* A, const float* xp,
                                       int srow, int sq, int grow_s, bool sv) {
    const float4* p = (const float4*)(xp + (size_t)grow_s * DH + sq * 32);
    #pragma unroll
    for (int q = 0; q < 8; q++) {
        float4 v = sv ? p[q] : make_float4(0.f, 0.f, 0.f, 0.f);
        int kp = sq * 16 + 2 * q;
        A[srow * APAD + kp]     = pack_h2(v.x, v.y);
        A[srow * APAD + kp + 1] = pack_h2(v.z, v.w);
    }
}

// single-pass MMA chunk; A from SMEM via ldmatrix, B fragments via __ldg
// (byte-identical to the verified R14 loop)
__device__ __forceinline__ void mma_chunk(float acc[2][4][4], uint32_t aL,
                                          const uint32_t* __restrict__ wf,
                                          int n8base, int l) {
    #pragma unroll 2
    for (int ks = 0; ks < 8; ks++) {
        uint2 bh[4];
        const uint32_t* base = wf + ks * 1024 + n8base * 64 + l * 2;
        #pragma unroll
        for (int nt = 0; nt < 4; nt++)
            bh[nt] = __ldg((const uint2*)(base + nt * 64));
        uint32_t ah[2][4];
        #pragma unroll
        for (int mt = 0; mt < 2; mt++)
            LDSM4(ah[mt], aL + mt * (16 * APAD * 4) + ks * 32);
        #pragma unroll
        for (int mt = 0; mt < 2; mt++)
            #pragma unroll
            for (int nt = 0; nt < 4; nt++)
                MMA16816(acc[mt][nt], ah[mt], bh[nt].x, bh[nt].y);
    }
}

// epilogue: silu(acc + bias) -> dst A buffer; resets acc (R14 formulas)
__device__ __forceinline__ void epi_silu(float acc[2][4][4], uint32_t* A,
                                         const float* __restrict__ bias,
                                         int warp_m, int warp_n,
                                         int er0, int ec, int ecp) {
    #pragma unroll
    for (int mt = 0; mt < 2; mt++)
        #pragma unroll
        for (int nt = 0; nt < 4; nt++) {
            int col = warp_n + 8 * nt + ec;
            float bb0 = __ldg(bias + col), bb1 = __ldg(bias + col + 1);
            int r0 = warp_m + 16 * mt + er0;
            int cp = ecp + 4 * nt;
            float h00 = silu_f(acc[mt][nt][0] + bb0);
            float h01 = silu_f(acc[mt][nt][1] + bb1);
            float h10 = silu_f(acc[mt][nt][2] + bb0);
            float h11 = silu_f(acc[mt][nt][3] + bb1);
            A[r0 * APAD + cp]       = pack_h2(h00, h01);
            A[(r0 + 8) * APAD + cp] = pack_h2(h10, h11);
            acc[mt][nt][0] = 0.f; acc[mt][nt][1] = 0.f;
            acc[mt][nt][2] = 0.f; acc[mt][nt][3] = 0.f;
        }
}

// ---------------- fused MLP kernel ----------------
__global__ void __launch_bounds__(256, 4)
mlp_kernel(const float* __restrict__ src, const float* __restrict__ dst,
           const float* __restrict__ edg,
           const float* __restrict__ b0, const float* __restrict__ b1,
           const float* __restrict__ b2,
           float* __restrict__ out, int E)
{
    __shared__ __align__(16) uint32_t sA[2 * A_U32];   // 34816 B: buf0 | buf1

    const int tid = threadIdx.x;
    const int l = tid & 31, w = tid >> 5;
    const int warp_m = (w & 1) * 32;
    const int warp_n = (w >> 1) * 32;
    const int n8base = (w >> 1) * 4;
    const int tile = blockIdx.x;

    // ldmatrix A per-lane offsets (verified mapping, R8/R9/R14)
    const int laneA_r = (l & 7) + ((l >> 3) & 1) * 8;
    const int laneA_k = ((l >> 4) & 1) * 4;
    const uint32_t aL0 = smem_u32p(sA) +
                         ((warp_m + laneA_r) * APAD + laneA_k) * 4;
    const uint32_t aL1 = aL0 + A_U32 * 4;

    float acc[2][4][4];
    #pragma unroll
    for (int mt = 0; mt < 2; mt++)
        #pragma unroll
        for (int nt = 0; nt < 4; nt++)
            #pragma unroll
            for (int q = 0; q < 4; q++) acc[mt][nt][q] = 0.f;

    // A staging map: 256 thr -> (row 0..63, 32-col quarter)
    const int srow = tid >> 2, sq = tid & 3;
    const int grow_s = tile * 64 + srow;
    const bool svalid = grow_s < E;

    // epilogue lane constants (R14 formulas)
    const int er0 = (l >> 2);
    const int ec  = (l & 3) * 2;
    const int ecp = (warp_n >> 1) + (l & 3);

    // ================= ping-pong schedule: 5 syncs per tile ================
    stageA(sA, edg, srow, sq, grow_s, svalid);
    __syncthreads();                               // buf0 ready

    // chunk 0 (edge @ W0[0:128]) reads buf0; stage src -> buf1 behind it
    mma_chunk(acc, aL0, &g_wf[0][0][0][0][0], n8base, l);
    stageA(sA + A_U32, src, srow, sq, grow_s, svalid);
    __syncthreads();                               // buf1 ready

    // chunk 1 (src @ W0[128:256]) reads buf1; stage dest -> buf0
    mma_chunk(acc, aL1, &g_wf[1][0][0][0][0], n8base, l);
    stageA(sA, dst, srow, sq, grow_s, svalid);
    __syncthreads();                               // buf0 ready

    // chunk 2 (dest @ W0[256:384]) reads buf0; epilogue0 writes buf1
    mma_chunk(acc, aL0, &g_wf[2][0][0][0][0], n8base, l);
    epi_silu(acc, sA + A_U32, b0, warp_m, warp_n, er0, ec, ecp);
    __syncthreads();                               // buf1 (h1) ready

    // layer 1 (h @ W1) reads buf1; epilogue1 writes buf0
    mma_chunk(acc, aL1, &g_wf[3][0][0][0][0], n8base, l);
    epi_silu(acc, sA, b1, warp_m, warp_n, er0, ec, ecp);
    __syncthreads();                               // buf0 (h2) ready

    // layer 2 (h @ W2) reads buf0; final epilogue -> out
    mma_chunk(acc, aL0, &g_wf[4][0][0][0][0], n8base, l);

    #pragma unroll
    for (int mt = 0; mt < 2; mt++)
        #pragma unroll
        for (int nt = 0; nt < 4; nt++) {
            int col = warp_n + 8 * nt + ec;
            float bb0 = __ldg(b2 + col), bb1 = __ldg(b2 + col + 1);
            int r0g = tile * 64 + warp_m + 16 * mt + er0;
            if (r0g < E) {
                float2 v = { acc[mt][nt][0] + bb0, acc[mt][nt][1] + bb1 };
                *(float2*)(out + (size_t)r0g * DH + col) = v;
            }
            if (r0g + 8 < E) {
                float2 v = { acc[mt][nt][2] + bb0, acc[mt][nt][3] + bb1 };
                *(float2*)(out + (size_t)(r0g + 8) * DH + col) = v;
            }
        }
}

// ---------------- host ----------------
extern "C" void kernel_launch(void* const* d_in, const int* in_sizes, int n_in,
                              void* d_out, int out_size) {
    const float* src = (const float*)d_in[0];
    const float* dst = (const float*)d_in[1];
    const float* edg = (const float*)d_in[2];
    const float* W0  = (const float*)d_in[3];
    const float* b0  = (const float*)d_in[4];
    const float* W1  = (const float*)d_in[5];
    const float* b1  = (const float*)d_in[6];
    const float* W2  = (const float*)d_in[7];
    const float* b2  = (const float*)d_in[8];

    int E = in_sizes[0] / DH;
    int ntiles = (E + 63) / 64;

    prep_weights<<<(40960 + 255) / 256, 256>>>(W0, W1, W2);
    mlp_kernel<<<ntiles, 256>>>(src, dst, edg, b0, b1, b2, (float*)d_out, E);
}